// round 15
// baseline (speedup 1.0000x reference)
#include <cuda_runtime.h>
#include <cstdint>

#define NN 50000
#define IC 256
#define DD 128
#define NH 8
#define HDIM 1024

#define TM 64                         // M tile
#define NTILES ((NN + TM - 1) / TM)   // 782

// Device scratch (allocation-free per harness rules)
__device__ float g_Wp[IC * DD];   // fragment-packed tf32 mean-V weight
__device__ float g_bm[DD];        // mean-over-heads V bias

__device__ __forceinline__ float to_tf32(float x) {
    float r; asm("cvt.rna.tf32.f32 %0, %1;" : "=f"(r) : "f"(x)); return r;
}
__device__ __forceinline__ uint32_t smem_to_u32(const void* p) {
    uint32_t a;
    asm("{ .reg .u64 t; cvta.to.shared.u64 t, %1; cvt.u32.u64 %0, t; }" : "=r"(a) : "l"(p));
    return a;
}

// mma.sync m16n8k8 tf32 (arch-agnostic PTX; HMMA on sm_103)
__device__ __forceinline__ void mma_tf32(float* d, const uint32_t* a, const uint32_t* b) {
    asm volatile(
        "mma.sync.aligned.m16n8k8.row.col.f32.tf32.tf32.f32 "
        "{%0,%1,%2,%3}, {%4,%5,%6,%7}, {%8,%9}, {%0,%1,%2,%3};"
        : "+f"(d[0]), "+f"(d[1]), "+f"(d[2]), "+f"(d[3])
        : "r"(a[0]), "r"(a[1]), "r"(a[2]), "r"(a[3]), "r"(b[0]), "r"(b[1]));
}

// ldmatrix x4: matrices = (rows0-7,k0-3),(rows8-15,k0-3),(rows0-7,k4-7),(rows8-15,k4-7)
__device__ __forceinline__ void ldsm_x4(uint32_t* a, uint32_t addr) {
    asm volatile("ldmatrix.sync.aligned.m8n8.x4.shared.b16 {%0,%1,%2,%3}, [%4];"
                 : "=r"(a[0]), "=r"(a[1]), "=r"(a[2]), "=r"(a[3]) : "r"(addr));
}

// ---------- prep: fragment-pack tf32(mean_h Wv), mean bias ----------
// element (k,d): c=k/32, ks=(k/8)%4, s=(k/4)%2, lane=(d%8)*4+(k%4),
// nt=d/8, wn=nt/4, jn=nt%4.
// g_Wp[c*4096 + wn*1024 + ks*256 + lane*8 + jn*2 + s]
//  -> per (warp,ks): lane reads 8 contiguous floats = 2x LDG.128
__global__ void prep_kernel(const float* __restrict__ Wv, const float* __restrict__ bv) {
    int e = blockIdx.x * 256 + threadIdx.x;     // 0..32767
    int k = e >> 7, d = e & 127;
    float s = 0.f;
#pragma unroll
    for (int h = 0; h < NH; h++) s += Wv[(size_t)k * HDIM + h * DD + d];
    int c = k >> 5, ks = (k >> 3) & 3, sb = (k >> 2) & 1;
    int lane = ((d & 7) << 2) | (k & 3);
    int nt = d >> 3, wn = nt >> 2, jn = nt & 3;
    g_Wp[c * 4096 + wn * 1024 + ks * 256 + lane * 8 + jn * 2 + sb] = to_tf32(s * 0.125f);
    if (e < DD) {
        float b = 0.f;
#pragma unroll
        for (int h = 0; h < NH; h++) b += bv[h * DD + e];
        g_bm[e] = b * 0.125f;
    }
}

// ---------- GEMM: out[50000,128] = X @ Wm + bm ----------
// 782 CTAs, tile 64x128, 8 warps 2(M)x4(N) -> warp 32x32, 4 CTAs/SM.
// A: 3-stage cp.async ring, one syncthreads per chunk.
// B: 2x LDG.128 per ks from packed g_Wp, software-pipelined ACROSS chunk
//    boundaries (loads issue before the MMAs that precede their use).
#define AS 36
#define ASTAGE (TM * AS)              // 2304 floats = 9216 B
#define RS 3
#define VSMEM (RS * ASTAGE * 4)       // 27648 B

__device__ __forceinline__ void issue_chunk(const float* __restrict__ X,
                                            uint32_t smBase, int m0, int c, int tid) {
    const uint32_t st = smBase + (c % RS) * (ASTAGE * 4);
#pragma unroll
    for (int i = 0; i < 2; i++) {
        int idx = tid + i * 256;            // 0..511 float4 slots
        int r = idx >> 3, q = idx & 7;
        int gr = m0 + r;
        int grc = (gr < NN) ? gr : (NN - 1);
        const float* src = X + (size_t)grc * IC + c * 32 + q * 4;
        unsigned sz = (gr < NN) ? 16u : 0u;   // OOB rows zero-filled
        asm volatile("cp.async.cg.shared.global [%0], [%1], 16, %2;"
                     :: "r"(st + (r * AS + q * 4) * 4), "l"(src), "r"(sz));
    }
}

// one warp's B fragments for a given (chunk, ks): 2 x LDG.128
__device__ __forceinline__ void load_b8(uint32_t* b, const float* __restrict__ p) {
    float4 lo = *(const float4*)(p);
    float4 hi = *(const float4*)(p + 4);
    b[0] = __float_as_uint(lo.x); b[1] = __float_as_uint(lo.y);
    b[2] = __float_as_uint(lo.z); b[3] = __float_as_uint(lo.w);
    b[4] = __float_as_uint(hi.x); b[5] = __float_as_uint(hi.y);
    b[6] = __float_as_uint(hi.z); b[7] = __float_as_uint(hi.w);
}

__global__ __launch_bounds__(256, 4) void vmean_gemm(const float* __restrict__ X,
                                                     float* __restrict__ out) {
    extern __shared__ float sm[];
    const uint32_t smBase = smem_to_u32(sm);

    const int tid = threadIdx.x;
    const int lane = tid & 31;
    const int wid = tid >> 5;
    const int warpM = wid >> 2;      // 0..1 (32 rows each)
    const int warpN = wid & 3;       // 0..3 (32 cols each)
    const int m0 = blockIdx.x * TM;

    // my warp's packed-B base: + chunk*4096 + ks*256 + lane*8
    const float* Wb = g_Wp + warpN * 1024 + lane * 8;

    // ldmatrix lane-address offsets (bytes, relative to stage base)
    const int rloc = lane & 15;
    const int col4 = (lane >> 4) << 2;
    uint32_t aRel[2];
#pragma unroll
    for (int mt = 0; mt < 2; mt++)
        aRel[mt] = ((warpM * 32 + mt * 16 + rloc) * AS + col4) * 4;

    // prologue: A chunks 0,1; B (chunk0, ks0)
    issue_chunk(X, smBase, m0, 0, tid);
    asm volatile("cp.async.commit_group;");
    issue_chunk(X, smBase, m0, 1, tid);
    asm volatile("cp.async.commit_group;");

    uint32_t bcur[8], bnxt[8];
    load_b8(bcur, Wb);

    float acc[2][4][4];
#pragma unroll
    for (int mt = 0; mt < 2; mt++)
#pragma unroll
        for (int jn = 0; jn < 4; jn++)
#pragma unroll
            for (int v = 0; v < 4; v++) acc[mt][jn][v] = 0.f;

#pragma unroll
    for (int g = 0; g < 8; g++) {
        asm volatile("cp.async.wait_group 1;");   // A chunk g landed
        __syncthreads();                          // publish to all warps

        // refill buf (g+2)%RS == (g-1)%RS (consumed last iter, fenced above)
        if (g + 2 < 8) issue_chunk(X, smBase, m0, g + 2, tid);
        asm volatile("cp.async.commit_group;");   // one group per iter

        const uint32_t stA = smBase + (g % RS) * (ASTAGE * 4);
#pragma unroll
        for (int ks = 0; ks < 4; ks++) {
            // prefetch next B (next ks, or next chunk's ks0; clamp at end)
            const int ng = (ks < 3) ? g : ((g < 7) ? g + 1 : 7);
            const int nks = (ks < 3) ? ks + 1 : 0;
            load_b8(bnxt, Wb + ng * 4096 + nks * 256);

            uint32_t a[2][4];
#pragma unroll
            for (int mt = 0; mt < 2; mt++)
                ldsm_x4(a[mt], stA + aRel[mt] + ks * 32);
#pragma unroll
            for (int mt = 0; mt < 2; mt++)
#pragma unroll
                for (int jn = 0; jn < 4; jn++)
                    mma_tf32(acc[mt][jn], a[mt], bcur + jn * 2);
#pragma unroll
            for (int v = 0; v < 8; v++) bcur[v] = bnxt[v];
        }
    }

    // epilogue: + bm, store
#pragma unroll
    for (int jn = 0; jn < 4; jn++) {
        int col = warpN * 32 + jn * 8 + 2 * (lane & 3);
        float2 bm2;
        bm2.x = g_bm[col];
        bm2.y = g_bm[col + 1];
#pragma unroll
        for (int mt = 0; mt < 2; mt++) {
            int row = m0 + warpM * 32 + mt * 16 + (lane >> 2);
            if (row < NN) {
                float2 o;
                o.x = acc[mt][jn][0] + bm2.x;
                o.y = acc[mt][jn][1] + bm2.y;
                *(float2*)(out + (size_t)row * DD + col) = o;
            }
            if (row + 8 < NN) {
                float2 o;
                o.x = acc[mt][jn][2] + bm2.x;
                o.y = acc[mt][jn][3] + bm2.y;
                *(float2*)(out + (size_t)(row + 8) * DD + col) = o;
            }
        }
    }
}

// ---------- launcher ----------
extern "C" void kernel_launch(void* const* d_in, const int* in_sizes, int n_in,
                              void* d_out, int out_size) {
    const float* xs = (const float*)d_in[1];   // source_input [N,256]
    const float* Wv = (const float*)d_in[6];
    const float* bv = (const float*)d_in[7];
    float* out = (float*)d_out;

    cudaFuncSetAttribute(vmean_gemm, cudaFuncAttributeMaxDynamicSharedMemorySize, VSMEM);

    prep_kernel<<<128, 256>>>(Wv, bv);
    vmean_gemm<<<NTILES, 256, VSMEM>>>(xs, out);
}

// round 16
// speedup vs baseline: 1.4681x; 1.4681x over previous
#include <cuda_runtime.h>
#include <cuda_fp16.h>
#include <cstdint>

#define NN 50000
#define IC 256
#define DD 128
#define NH 8
#define HDIM 1024

#define TM 64                         // M tile
#define NTILES ((NN + TM - 1) / TM)   // 782

// Device scratch (allocation-free per harness rules)
__device__ __half g_Wph[IC * DD];   // fragment-packed fp16 mean-V weight (64KB)
__device__ float  g_bm[DD];         // mean-over-heads V bias

__device__ __forceinline__ uint32_t smem_to_u32(const void* p) {
    uint32_t a;
    asm("{ .reg .u64 t; cvta.to.shared.u64 t, %1; cvt.u32.u64 %0, t; }" : "=r"(a) : "l"(p));
    return a;
}

// mma.sync m16n8k16 fp16 (arch-agnostic PTX; HMMA.16816 on sm_103)
//  A (4 regs), B (2 regs), D fp32 (4 regs); layouts are the canonical PTX ones.
__device__ __forceinline__ void mma_f16(float* d, const uint32_t* a, const uint32_t* b) {
    asm volatile(
        "mma.sync.aligned.m16n8k16.row.col.f32.f16.f16.f32 "
        "{%0,%1,%2,%3}, {%4,%5,%6,%7}, {%8,%9}, {%0,%1,%2,%3};"
        : "+f"(d[0]), "+f"(d[1]), "+f"(d[2]), "+f"(d[3])
        : "r"(a[0]), "r"(a[1]), "r"(a[2]), "r"(a[3]), "r"(b[0]), "r"(b[1]));
}

// ldmatrix x4 b16: lanes 0-15 give rows 0-15 (k lo 16B), lanes 16-31 rows 0-15 (k hi 16B)
__device__ __forceinline__ void ldsm_x4(uint32_t* a, uint32_t addr) {
    asm volatile("ldmatrix.sync.aligned.m8n8.x4.shared.b16 {%0,%1,%2,%3}, [%4];"
                 : "=r"(a[0]), "=r"(a[1]), "=r"(a[2]), "=r"(a[3]) : "r"(addr));
}

__device__ __forceinline__ void lds128(uint32_t* r, uint32_t addr) {
    asm volatile("ld.shared.v4.u32 {%0,%1,%2,%3}, [%4];"
                 : "=r"(r[0]), "=r"(r[1]), "=r"(r[2]), "=r"(r[3]) : "r"(addr));
}

// ---------- prep: fragment-pack fp16(mean_h Wv) with baked SW128; mean bias ----------
// element (k,d): c=k/32, s16=(k%32)/16, kl=k%16; wn=d/32, jn=(d/8)%4, nl=d%8.
// B-frag lane = nl*4 + (kl%8)/2 ; pos = (kl/8)*2 + kl%2.
// inner byte off (within 1KB (wn,s16) block) = lane*32 + jn*8 + pos*2, stored at
// inner ^ ((inner>>3)&0x70)  -> kernel reads 2 conflict-free LDS.128 per (wn,s16).
__global__ void prep_kernel(const float* __restrict__ Wv, const float* __restrict__ bv) {
    int e = blockIdx.x * 256 + threadIdx.x;     // 0..32767
    int k = e >> 7, d = e & 127;
    float s = 0.f;
#pragma unroll
    for (int h = 0; h < NH; h++) s += Wv[(size_t)k * HDIM + h * DD + d];
    __half hv = __float2half_rn(s * 0.125f);

    int c = k >> 5, kk = k & 31, s16 = kk >> 4, kl = kk & 15;
    int lane = ((d & 7) << 2) | ((kl & 7) >> 1);
    int pos = ((kl >> 3) & 1) * 2 + (kl & 1);
    int jn = (d >> 3) & 3, wn = d >> 5;
    int inner = lane * 32 + jn * 8 + pos * 2;
    int sw = inner ^ ((inner >> 3) & 0x70);
    g_Wph[(c * 8192 + wn * 2048 + s16 * 1024 + sw) >> 1] = hv;

    if (e < DD) {
        float b = 0.f;
#pragma unroll
        for (int h = 0; h < NH; h++) b += bv[h * DD + e];
        g_bm[e] = b * 0.125f;
    }
}

// ---------- GEMM: out[50000,128] = fp16(X) @ fp16(Wm) + bm (fp32 accum) ----------
// 782 CTAs, tile 64x128, 8 warps 2(M)x4(N) -> warp 32x32. 3 CTAs/SM.
// Ring RS=3: A (64x32 fp16, row stride 40 halves, via LDG->cvt->STS, 2-chunk reg
// prefetch) + W (8KB packed fp16 via cp.async). One __syncthreads per chunk.
#define AROWB 80                       // bytes per A row (40 halves)
#define ABYTES (TM * AROWB)            // 5120
#define WBYTES 8192
#define STB (ABYTES + WBYTES)          // 13312
#define RS 3
#define VSMEM (RS * STB)               // 39936

__device__ __forceinline__ void ldgA(const float* __restrict__ X, float4* R,
                                     int m0, int c, int tid) {
#pragma unroll
    for (int i = 0; i < 2; i++) {
        int idx = tid + i * 256;            // 0..511 float4 slots
        int r = idx >> 3, q = idx & 7;
        int gr = m0 + r;
        int grc = (gr < NN) ? gr : (NN - 1);
        R[i] = *(const float4*)(X + (size_t)grc * IC + c * 32 + q * 4);
    }
}

__device__ __forceinline__ void stsA(const float4* R, uint32_t smBase, int st, int tid) {
    const uint32_t base = smBase + st * STB;
#pragma unroll
    for (int i = 0; i < 2; i++) {
        int idx = tid + i * 256;
        int r = idx >> 3, q = idx & 7;
        __half2 h0 = __floats2half2_rn(R[i].x, R[i].y);
        __half2 h1 = __floats2half2_rn(R[i].z, R[i].w);
        uint32_t u0 = *(uint32_t*)&h0, u1 = *(uint32_t*)&h1;
        asm volatile("st.shared.v2.u32 [%0], {%1, %2};"
                     :: "r"(base + r * AROWB + q * 8), "r"(u0), "r"(u1) : "memory");
    }
}

__device__ __forceinline__ void cpW(uint32_t smBase, int st, int c, int tid) {
    const uint32_t dst = smBase + st * STB + ABYTES;
    const char* src = (const char*)g_Wph + c * 8192;
#pragma unroll
    for (int i = 0; i < 2; i++) {
        int o = (tid + i * 256) * 16;
        asm volatile("cp.async.cg.shared.global [%0], [%1], 16;"
                     :: "r"(dst + o), "l"(src + o));
    }
}

__global__ __launch_bounds__(256, 3) void vmean_gemm(const float* __restrict__ X,
                                                     float* __restrict__ out) {
    extern __shared__ char smc[];
    const uint32_t smBase = smem_to_u32(smc);

    const int tid = threadIdx.x;
    const int lane = tid & 31;
    const int wid = tid >> 5;
    const int warpM = wid >> 2;      // 0..1 (32 rows each)
    const int warpN = wid & 3;       // 0..3 (32 cols each)
    const int m0 = blockIdx.x * TM;

    // ldmatrix lane offsets (bytes, rel. to stage A base): rows lane&15, k-half lane>>4
    const int rloc = lane & 15;
    const int khalf = (lane >> 4) << 4;    // 0 or 16 bytes
    uint32_t aRel[2];
#pragma unroll
    for (int mt = 0; mt < 2; mt++)
        aRel[mt] = (warpM * 32 + mt * 16 + rloc) * AROWB + khalf;

    // B smem read offset (swizzled), rel. to stage W base
    const uint32_t bRel = (uint32_t)(warpN * 2048 + ((lane * 32) ^ (((lane >> 2) & 7) << 4)));

    float4 R[2][2];
    // prologue: A0 ldg+sts, A1 ldg; W0,W1 cp.async
    ldgA(X, R[0], m0, 0, tid);
    stsA(R[0], smBase, 0, tid);
    ldgA(X, R[1], m0, 1, tid);
    cpW(smBase, 0, 0, tid);
    asm volatile("cp.async.commit_group;");
    cpW(smBase, 1, 1, tid);
    asm volatile("cp.async.commit_group;");

    float acc[2][4][4];
#pragma unroll
    for (int mt = 0; mt < 2; mt++)
#pragma unroll
        for (int jn = 0; jn < 4; jn++)
#pragma unroll
            for (int v = 0; v < 4; v++) acc[mt][jn][v] = 0.f;

#pragma unroll
    for (int g = 0; g < 8; g++) {
        asm volatile("cp.async.wait_group 1;");   // W g landed
        __syncthreads();                          // publishes W g + A g

        if (g + 1 < 8) stsA(R[(g + 1) & 1], smBase, (g + 1) % RS, tid);
        if (g + 2 < 8) {
            ldgA(X, R[g & 1], m0, g + 2, tid);
            cpW(smBase, (g + 2) % RS, g + 2, tid);
        }
        asm volatile("cp.async.commit_group;");   // one group per iter

        const uint32_t stA = smBase + (g % RS) * STB;
        const uint32_t stW = stA + ABYTES;
#pragma unroll
        for (int s = 0; s < 2; s++) {             // two k16 steps per 32-k chunk
            uint32_t b[8];
            uint32_t ba = stW + bRel + s * 1024;
            lds128(b, ba);                        // jn0 (b0,b1), jn1 (b0,b1)
            lds128(b + 4, ba ^ 16);               // jn2, jn3
            uint32_t a[2][4];
#pragma unroll
            for (int mt = 0; mt < 2; mt++)
                ldsm_x4(a[mt], stA + aRel[mt] + s * 32);
#pragma unroll
            for (int mt = 0; mt < 2; mt++)
#pragma unroll
                for (int jn = 0; jn < 4; jn++)
                    mma_f16(acc[mt][jn], a[mt], b + jn * 2);
        }
    }

    // epilogue: + bm, store
#pragma unroll
    for (int jn = 0; jn < 4; jn++) {
        int col = warpN * 32 + jn * 8 + 2 * (lane & 3);
        float2 bm2;
        bm2.x = g_bm[col];
        bm2.y = g_bm[col + 1];
#pragma unroll
        for (int mt = 0; mt < 2; mt++) {
            int row = m0 + warpM * 32 + mt * 16 + (lane >> 2);
            if (row < NN) {
                float2 o;
                o.x = acc[mt][jn][0] + bm2.x;
                o.y = acc[mt][jn][1] + bm2.y;
                *(float2*)(out + (size_t)row * DD + col) = o;
            }
            if (row + 8 < NN) {
                float2 o;
                o.x = acc[mt][jn][2] + bm2.x;
                o.y = acc[mt][jn][3] + bm2.y;
                *(float2*)(out + (size_t)(row + 8) * DD + col) = o;
            }
        }
    }
}

// ---------- launcher ----------
extern "C" void kernel_launch(void* const* d_in, const int* in_sizes, int n_in,
                              void* d_out, int out_size) {
    const float* xs = (const float*)d_in[1];   // source_input [N,256]
    const float* Wv = (const float*)d_in[6];
    const float* bv = (const float*)d_in[7];
    float* out = (float*)d_out;

    cudaFuncSetAttribute(vmean_gemm, cudaFuncAttributeMaxDynamicSharedMemorySize, VSMEM);

    prep_kernel<<<128, 256>>>(Wv, bv);
    vmean_gemm<<<NTILES, 256, VSMEM>>>(xs, out);
}